// round 1
// baseline (speedup 1.0000x reference)
#include <cuda_runtime.h>
#include <cstdint>

// ---------------- problem constants ----------------
#define HW     4096      // 64*64
#define IMGW   64
#define BATCH  16
#define CIN    256
#define C3     768       // qkv channels
#define CCAT   512       // attention output channels
#define COUT   256
#define NHEAD  64
#define DIMH   8
#define ATT_EPS 1e-5f

// ---------------- scratch (device globals; no allocations) ----------------
__device__ float g_qkv [(size_t)BATCH * C3   * HW];   // relu(bn(conv1x1(x)))
__device__ float g_agg [(size_t)BATCH * C3   * HW];   // depthwise+pointwise agg
__device__ float g_attn[(size_t)BATCH * CCAT * HW];   // attention output
__device__ float g_vk  [BATCH * NHEAD * 72];          // per-head vk(64) + ksum(8)

// ==========================================================================
// Fused 1x1-conv GEMM + BN + ReLU.
//   Out[b, m, n] = relu( scale[m] * sum_k W[m,k] * X[b,k,n] + bias[m] )
// BM=BN=128, BK=8, 256 threads, 8x8 per-thread micro-tile.
// PROJ=false: X = external x input, Out = g_qkv
// PROJ=true : X = g_attn,           Out = external d_out
// ==========================================================================
template<int Mt, int Kt, bool PROJ>
__global__ __launch_bounds__(256)
void gemm_bn_relu_kernel(const float* __restrict__ Xext,
                         const float* __restrict__ Wm,
                         const float* __restrict__ scale,
                         const float* __restrict__ bias,
                         float* __restrict__ OutExt)
{
    __shared__ float As[8][128];
    __shared__ float Bs[8][128];

    const float* __restrict__ X   = PROJ ? g_attn : Xext;
    float*       __restrict__ Out = PROJ ? OutExt : g_qkv;

    const int b     = blockIdx.z;
    const int mBase = blockIdx.y * 128;
    const int nBase = blockIdx.x * 128;
    const int tid   = threadIdx.x;
    const int tx    = tid & 15;       // 0..15 -> 8 cols each
    const int ty    = tid >> 4;       // 0..15 -> 8 rows each

    const float* __restrict__ Xb = X + (size_t)b * Kt * HW;

    float acc[8][8];
    #pragma unroll
    for (int i = 0; i < 8; i++)
        #pragma unroll
        for (int j = 0; j < 8; j++) acc[i][j] = 0.f;

    const int aRow = tid >> 1;          // 0..127
    const int aCol = (tid & 1) * 4;     // 0 or 4
    const int bRow = tid >> 5;          // 0..7
    const int bCol = (tid & 31) * 4;    // 0..124

    for (int k0 = 0; k0 < Kt; k0 += 8) {
        // A tile: W [Mt,Kt] row-major -> As[k][m] (transposed)
        float4 a4 = *reinterpret_cast<const float4*>(
            &Wm[(size_t)(mBase + aRow) * Kt + k0 + aCol]);
        As[aCol + 0][aRow] = a4.x;
        As[aCol + 1][aRow] = a4.y;
        As[aCol + 2][aRow] = a4.z;
        As[aCol + 3][aRow] = a4.w;
        // B tile: X [Kt, HW] -> Bs[k][n]
        float4 b4 = *reinterpret_cast<const float4*>(
            &Xb[(size_t)(k0 + bRow) * HW + nBase + bCol]);
        *reinterpret_cast<float4*>(&Bs[bRow][bCol]) = b4;
        __syncthreads();

        #pragma unroll
        for (int kk = 0; kk < 8; kk++) {
            float a[8], bb[8];
            #pragma unroll
            for (int i = 0; i < 8; i++) a[i]  = As[kk][ty * 8 + i];
            #pragma unroll
            for (int j = 0; j < 8; j++) bb[j] = Bs[kk][tx * 8 + j];
            #pragma unroll
            for (int i = 0; i < 8; i++)
                #pragma unroll
                for (int j = 0; j < 8; j++)
                    acc[i][j] = fmaf(a[i], bb[j], acc[i][j]);
        }
        __syncthreads();
    }

    // epilogue: BN (scale/bias) + ReLU, float4 stores
    #pragma unroll
    for (int i = 0; i < 8; i++) {
        const int m = mBase + ty * 8 + i;
        const float sc = scale[m], bi = bias[m];
        float* orow = Out + (size_t)b * Mt * HW + (size_t)m * HW + nBase + tx * 8;
        #pragma unroll
        for (int j = 0; j < 8; j += 4) {
            float4 v;
            v.x = fmaxf(fmaf(acc[i][j + 0], sc, bi), 0.f);
            v.y = fmaxf(fmaf(acc[i][j + 1], sc, bi), 0.f);
            v.z = fmaxf(fmaf(acc[i][j + 2], sc, bi), 0.f);
            v.w = fmaxf(fmaf(acc[i][j + 3], sc, bi), 0.f);
            *reinterpret_cast<float4*>(orow + j) = v;
        }
    }
}

// ==========================================================================
// Fused depthwise 5x5 (pad 2, +bias) then per-channel 1x1 (*w, +bias).
//   g_agg[b,c,p] = (dw5x5(g_qkv)[b,c,p] + dw_b[c]) * pw_w[c] + pw_b[c]
// ==========================================================================
__global__ __launch_bounds__(256)
void dw5x5_pw_kernel(const float* __restrict__ dw_w,   // [C3, 25]
                     const float* __restrict__ dw_b,   // [C3]
                     const float* __restrict__ pw_w,   // [C3]
                     const float* __restrict__ pw_b)   // [C3]
{
    const int c = blockIdx.y;
    const int b = blockIdx.z;
    const int p = blockIdx.x * 256 + threadIdx.x;   // 0..4095
    const int y = p >> 6;
    const int x = p & 63;

    const float* __restrict__ src = g_qkv + ((size_t)b * C3 + c) * HW;

    float wreg[25];
    #pragma unroll
    for (int i = 0; i < 25; i++) wreg[i] = __ldg(&dw_w[c * 25 + i]);

    float s = 0.f;
    #pragma unroll
    for (int dy = 0; dy < 5; dy++) {
        const int yy = y + dy - 2;
        if (yy < 0 || yy >= IMGW) continue;
        const float* row = src + yy * IMGW;
        #pragma unroll
        for (int dx = 0; dx < 5; dx++) {
            const int xx = x + dx - 2;
            if (xx < 0 || xx >= IMGW) continue;
            s = fmaf(__ldg(&row[xx]), wreg[dy * 5 + dx], s);
        }
    }
    s = fmaf(s + __ldg(&dw_b[c]), __ldg(&pw_w[c]), __ldg(&pw_b[c]));
    g_agg[((size_t)b * C3 + c) * HW + p] = s;
}

// ==========================================================================
// Attention phase 1: per (b, head) reduce over N=4096:
//   vk[d][e] = sum_n v[d,n] * relu(k[e,n]);  ksum[e] = sum_n relu(k[e,n])
// Heads 0..31 read from g_qkv, heads 32..63 from g_agg.
// Per head, channels: [0..7]=q, [8..15]=k, [16..23]=v.
// ==========================================================================
__global__ __launch_bounds__(256)
void attn_reduce_kernel()
{
    const int head = blockIdx.x;
    const int b    = blockIdx.y;
    const float* __restrict__ src = (head < 32) ? g_qkv : g_agg;
    const int ch0 = (head & 31) * 24;
    const float* __restrict__ base = src + ((size_t)b * C3 + ch0) * HW;

    float acc[72];
    #pragma unroll
    for (int i = 0; i < 72; i++) acc[i] = 0.f;

    for (int n = threadIdx.x; n < HW; n += 256) {
        float kv[8], vv[8];
        #pragma unroll
        for (int e = 0; e < 8; e++) kv[e] = fmaxf(base[(size_t)(8 + e) * HW + n], 0.f);
        #pragma unroll
        for (int d = 0; d < 8; d++) vv[d] = base[(size_t)(16 + d) * HW + n];
        #pragma unroll
        for (int d = 0; d < 8; d++)
            #pragma unroll
            for (int e = 0; e < 8; e++)
                acc[d * 8 + e] = fmaf(vv[d], kv[e], acc[d * 8 + e]);
        #pragma unroll
        for (int e = 0; e < 8; e++) acc[64 + e] += kv[e];
    }

    __shared__ float s_acc[72];
    if (threadIdx.x < 72) s_acc[threadIdx.x] = 0.f;
    __syncthreads();

    const int lane = threadIdx.x & 31;
    #pragma unroll
    for (int i = 0; i < 72; i++) {
        float v = acc[i];
        #pragma unroll
        for (int off = 16; off > 0; off >>= 1)
            v += __shfl_down_sync(0xffffffffu, v, off);
        if (lane == 0) atomicAdd(&s_acc[i], v);
    }
    __syncthreads();
    if (threadIdx.x < 72)
        g_vk[((size_t)b * NHEAD + head) * 72 + threadIdx.x] = s_acc[threadIdx.x];
}

// ==========================================================================
// Attention phase 2: per position apply
//   out[d,n] = (sum_e vk[d][e]*relu(q[e,n])) / (sum_e ksum[e]*relu(q[e,n]) + eps)
// writes g_attn[b, head*8+d, n]
// ==========================================================================
__global__ __launch_bounds__(256)
void attn_apply_kernel()
{
    const int head = blockIdx.y;
    const int b    = blockIdx.z;
    const int n    = blockIdx.x * 256 + threadIdx.x;

    __shared__ float s[72];
    if (threadIdx.x < 72)
        s[threadIdx.x] = g_vk[((size_t)b * NHEAD + head) * 72 + threadIdx.x];
    __syncthreads();

    const float* __restrict__ src = (head < 32) ? g_qkv : g_agg;
    const int ch0 = (head & 31) * 24;
    const float* __restrict__ base = src + ((size_t)b * C3 + ch0) * HW;

    float q[8];
    #pragma unroll
    for (int e = 0; e < 8; e++) q[e] = fmaxf(base[(size_t)e * HW + n], 0.f);

    float denom = ATT_EPS;
    #pragma unroll
    for (int e = 0; e < 8; e++) denom = fmaf(s[64 + e], q[e], denom);
    const float inv = 1.f / denom;

    float* obase = g_attn + ((size_t)b * CCAT + head * 8) * HW + n;
    #pragma unroll
    for (int d = 0; d < 8; d++) {
        float o = 0.f;
        #pragma unroll
        for (int e = 0; e < 8; e++) o = fmaf(s[d * 8 + e], q[e], o);
        obase[(size_t)d * HW] = o * inv;
    }
}

// ==========================================================================
// launcher
// ==========================================================================
extern "C" void kernel_launch(void* const* d_in, const int* in_sizes, int n_in,
                              void* d_out, int out_size)
{
    const float* x            = (const float*)d_in[0];   // (16,256,64,64)
    const float* qkv_w        = (const float*)d_in[1];   // (768,256,1,1)
    const float* qkv_bn_scale = (const float*)d_in[2];   // (768)
    const float* qkv_bn_bias  = (const float*)d_in[3];   // (768)
    const float* agg_dw_w     = (const float*)d_in[4];   // (768,1,5,5)
    const float* agg_dw_b     = (const float*)d_in[5];   // (768)
    const float* agg_pw_w     = (const float*)d_in[6];   // (768,1,1,1)
    const float* agg_pw_b     = (const float*)d_in[7];   // (768)
    const float* proj_w       = (const float*)d_in[8];   // (256,512,1,1)
    const float* proj_bn_scale= (const float*)d_in[9];   // (256)
    const float* proj_bn_bias = (const float*)d_in[10];  // (256)
    float* out = (float*)d_out;                          // (16,256,64,64)

    // 1) qkv = relu(bn(conv1x1(x)))  -> g_qkv
    {
        dim3 grid(HW / 128, C3 / 128, BATCH);
        gemm_bn_relu_kernel<C3, CIN, false><<<grid, 256>>>(
            x, qkv_w, qkv_bn_scale, qkv_bn_bias, nullptr);
    }
    // 2) agg = pw(dw5x5(qkv)) -> g_agg
    {
        dim3 grid(HW / 256, C3, BATCH);
        dw5x5_pw_kernel<<<grid, 256>>>(agg_dw_w, agg_dw_b, agg_pw_w, agg_pw_b);
    }
    // 3a) per-head vk / ksum reduction
    {
        dim3 grid(NHEAD, BATCH);
        attn_reduce_kernel<<<grid, 256>>>();
    }
    // 3b) apply + normalize -> g_attn
    {
        dim3 grid(HW / 256, NHEAD, BATCH);
        attn_apply_kernel<<<grid, 256>>>();
    }
    // 4) out = relu(bn(conv1x1(g_attn)))
    {
        dim3 grid(HW / 128, COUT / 128, BATCH);
        gemm_bn_relu_kernel<COUT, CCAT, true><<<grid, 256>>>(
            nullptr, proj_w, proj_bn_scale, proj_bn_bias, out);
    }
}